// round 11
// baseline (speedup 1.0000x reference)
#include <cuda_runtime.h>
#include <math.h>
#include <float.h>

// Problem constants
#define NB 8
#define NN 2048
#define NC 128
#define NCH 128     // chunks per batch
#define CSZ 16      // chunk size (NCH*CSZ == NN)
#define NP (NN+1)   // prefix length 2049

// ---------------- scratch (device globals; no allocation) ----------------
__device__ float g_h[NB*NN*NC];        // h = text @ W
__device__ float g_s1[NB*NN];
__device__ float g_s2[NB*NN];
__device__ float g_s2s[NB*NN];         // sorted s2 (ascending, via rank scatter)
__device__ int   g_perm[NB*NN];        // permutation of sort
__device__ float g_wA[NB*NN];          // e^{s2s - m2}
__device__ float g_wB[NB*NN];          // e^{0.2(s2s - m2)}
__device__ float g_m2[NB];
__device__ float2 g_ch[NB*(NCH+1)*NC]; // chunk aggregates -> exclusive bases; [NCH]=totals
__device__ float g_paf[NB*NP];         // full scalar exclusive prefix of wA; [2048]=total
__device__ float g_pbf[NB*NP];
__device__ float2 g_P[NB*NP*NC];       // intra-chunk RELATIVE vector prefixes (x=A, y=B)

// ---------------- f32x2 packed-FMA helpers (sm_103a FFMA2) ----------------
__device__ __forceinline__ unsigned long long pack2(float x, float y) {
    unsigned long long r;
    asm("mov.b64 %0, {%1, %2};" : "=l"(r) : "f"(x), "f"(y));
    return r;
}
__device__ __forceinline__ void unpack2(unsigned long long v, float& x, float& y) {
    asm("mov.b64 {%0, %1}, %2;" : "=f"(x), "=f"(y) : "l"(v));
}
__device__ __forceinline__ void ffma2(unsigned long long& d, unsigned long long a, unsigned long long b) {
    asm("fma.rn.f32x2 %0, %1, %2, %0;" : "+l"(d) : "l"(a), "l"(b));
}

// ---------------- Kernel 1: GEMM h = text@W (f32x2), fused s1/s2 ----------------
__global__ void __launch_bounds__(256) gemm_kernel(const float* __restrict__ A,
                                                   const float* __restrict__ W,
                                                   const float* __restrict__ avec)
{
    __shared__ float As[16][64];
    __shared__ float Bs[16][128];
    const int b  = blockIdx.y;
    const int m0 = blockIdx.x * 64;
    const int tid = threadIdx.x;
    const int tx = tid & 31;
    const int ty = tid >> 5;
    const float* Ab = A + (size_t)(b*NN + m0) * NC;

    unsigned long long acc2[4][4];
#pragma unroll
    for (int p = 0; p < 4; p++)
#pragma unroll
        for (int j = 0; j < 4; j++) acc2[p][j] = 0ull;

    const int ar = tid >> 2;
    const int ac = (tid & 3) * 4;

    for (int k0 = 0; k0 < 128; k0 += 16) {
        float4 av = *(const float4*)(Ab + (size_t)ar*NC + k0 + ac);
        As[ac+0][ar] = av.x; As[ac+1][ar] = av.y;
        As[ac+2][ar] = av.z; As[ac+3][ar] = av.w;
#pragma unroll
        for (int it = 0; it < 2; it++) {
            int idx = tid + 256*it;
            int brr = idx >> 5, bcc = (idx & 31) * 4;
            *(float4*)&Bs[brr][bcc] = *(const float4*)(W + (size_t)(k0+brr)*NC + bcc);
        }
        __syncthreads();
#pragma unroll
        for (int kk = 0; kk < 16; kk++) {
            float4 a03 = *(const float4*)&As[kk][ty*8];
            float4 a47 = *(const float4*)&As[kk][ty*8 + 4];
            float4 bv  = *(const float4*)&Bs[kk][tx*4];
            unsigned long long ap[4];
            ap[0] = pack2(a03.x, a03.y); ap[1] = pack2(a03.z, a03.w);
            ap[2] = pack2(a47.x, a47.y); ap[3] = pack2(a47.z, a47.w);
            unsigned long long bd[4];
            bd[0] = pack2(bv.x, bv.x); bd[1] = pack2(bv.y, bv.y);
            bd[2] = pack2(bv.z, bv.z); bd[3] = pack2(bv.w, bv.w);
#pragma unroll
            for (int p = 0; p < 4; p++)
#pragma unroll
                for (int j = 0; j < 4; j++) ffma2(acc2[p][j], ap[p], bd[j]);
        }
        __syncthreads();
    }

    float acc[8][4];
#pragma unroll
    for (int p = 0; p < 4; p++)
#pragma unroll
        for (int j = 0; j < 4; j++) unpack2(acc2[p][j], acc[2*p][j], acc[2*p+1][j]);

    float a1[4], a2[4];
#pragma unroll
    for (int j = 0; j < 4; j++) { a1[j] = avec[tx*4+j]; a2[j] = avec[128 + tx*4+j]; }

#pragma unroll
    for (int i = 0; i < 8; i++) {
        int row = m0 + ty*8 + i;
        float4 v = make_float4(acc[i][0], acc[i][1], acc[i][2], acc[i][3]);
        *(float4*)(g_h + (size_t)(b*NN + row)*NC + tx*4) = v;
        float d1 = acc[i][0]*a1[0] + acc[i][1]*a1[1] + acc[i][2]*a1[2] + acc[i][3]*a1[3];
        float d2 = acc[i][0]*a2[0] + acc[i][1]*a2[1] + acc[i][2]*a2[2] + acc[i][3]*a2[3];
#pragma unroll
        for (int off = 16; off > 0; off >>= 1) {
            d1 += __shfl_down_sync(0xffffffffu, d1, off);
            d2 += __shfl_down_sync(0xffffffffu, d2, off);
        }
        if (tx == 0) { g_s1[b*NN + row] = d1; g_s2[b*NN + row] = d2; }
    }
}

// ---------------- Kernel 2: rank-scatter "sort" (whole-chip parallel) ----------------
__global__ void __launch_bounds__(128) rank_kernel()
{
    __shared__ float keys[NN];
    __shared__ float red[4];
    const int b = blockIdx.y, tid = threadIdx.x;
    const int j = blockIdx.x * 128 + tid;

    for (int i = tid; i < NN; i += 128) keys[i] = g_s2[b*NN + i];
    __syncthreads();

    float mx = -FLT_MAX;
    for (int i = tid; i < NN; i += 128) mx = fmaxf(mx, keys[i]);
#pragma unroll
    for (int off = 16; off > 0; off >>= 1)
        mx = fmaxf(mx, __shfl_xor_sync(0xffffffffu, mx, off));
    if ((tid & 31) == 0) red[tid >> 5] = mx;
    __syncthreads();
    const float m2v = fmaxf(fmaxf(red[0], red[1]), fmaxf(red[2], red[3]));
    if (blockIdx.x == 0 && tid == 0) g_m2[b] = m2v;

    const float k = keys[j];
    const float4* k4 = (const float4*)keys;
    int rank = 0;
#pragma unroll 4
    for (int q = 0; q < NN/4; q++) {
        float4 v = k4[q];
        int jj = q*4;
        rank += (v.x < k) || (v.x == k && jj+0 < j);
        rank += (v.y < k) || (v.y == k && jj+1 < j);
        rank += (v.z < k) || (v.z == k && jj+2 < j);
        rank += (v.w < k) || (v.w == k && jj+3 < j);
    }

    const float s = k - m2v;
    const int o = b*NN + rank;
    g_s2s[o]  = k;
    g_perm[o] = j;
    g_wA[o]   = expf(s);
    g_wB[o]   = expf(0.2f * s);
}

// ---------------- Kernel 3: relative expand (single pass over h) ----------------
__global__ void __launch_bounds__(128) relexpand_kernel()
{
    __shared__ float wa[CSZ], wb[CSZ];
    __shared__ int js[CSZ];
    const int b = blockIdx.y, c = blockIdx.x, f = threadIdx.x;
    const int base = b*NN + c*CSZ;
    if (f < CSZ) {
        wa[f] = g_wA[base + f];
        wb[f] = g_wB[base + f];
        js[f] = g_perm[base + f];
    }
    __syncthreads();

    float hv[CSZ];
#pragma unroll
    for (int r = 0; r < CSZ; r++) hv[r] = g_h[(size_t)(b*NN + js[r])*NC + f];

    float runA = 0.f, runB = 0.f;
    size_t p = (size_t)(b*NP + c*CSZ)*NC + f;
#pragma unroll
    for (int r = 0; r < CSZ; r++) {
        g_P[p] = make_float2(runA, runB);
        runA = fmaf(wa[r], hv[r], runA);
        runB = fmaf(wb[r], hv[r], runB);
        p += NC;
    }
    g_ch[(size_t)(b*(NCH+1)+c)*NC + f] = make_float2(runA, runB);
    if (c == NCH-1) g_P[p] = make_float2(0.f, 0.f);
}

// ---------------- Kernel 4: wide fused chunk-scan + scalar weight prefixes ----------------
// grid (NB, 17) x 256. Blocks y=0..15: warp-per-feature chunk scan
// (16 blocks x 8 warps = 128 features). Block y=16: scalar weight prefixes.
__global__ void __launch_bounds__(256) scanspf_kernel()
{
    const int b = blockIdx.x;

    if (blockIdx.y < 16) {
        // --- warp-per-feature exclusive scan over 128 chunk aggregates ---
        const int w = threadIdx.x >> 5, lane = threadIdx.x & 31;
        const int f = blockIdx.y * 8 + w;
        const size_t base = (size_t)(b*(NCH+1))*NC + f;

        float2 v[4];
#pragma unroll
        for (int u = 0; u < 4; u++) v[u] = g_ch[base + (size_t)(lane*4+u)*NC];

        float ownA = (v[0].x + v[1].x) + (v[2].x + v[3].x);
        float ownB = (v[0].y + v[1].y) + (v[2].y + v[3].y);
        float sA = ownA, sB = ownB;
#pragma unroll
        for (int off = 1; off < 32; off <<= 1) {
            float nA = __shfl_up_sync(0xffffffffu, sA, off);
            float nB = __shfl_up_sync(0xffffffffu, sB, off);
            if (lane >= off) { sA += nA; sB += nB; }
        }
        float eA = sA - ownA, eB = sB - ownB;
#pragma unroll
        for (int u = 0; u < 4; u++) {
            float2 cur = v[u];
            g_ch[base + (size_t)(lane*4+u)*NC] = make_float2(eA, eB);
            eA += cur.x; eB += cur.y;
        }
        if (lane == 31) g_ch[base + (size_t)NCH*NC] = make_float2(sA, sB);
    } else {
        // --- scalar weight prefixes (threads 0..127 active) ---
        __shared__ float sa_sh[4], sb_sh[4];
        const int t = threadIdx.x;
        float va[CSZ], vb[CSZ];
        float sa = 0.f, sb = 0.f, ia = 0.f, ib = 0.f;
        if (t < 128) {
            const int c = t;
            const int lane = c & 31, w = c >> 5;
            const int wbase = b*NN + c*CSZ;
#pragma unroll
            for (int r = 0; r < CSZ; r++) {
                va[r] = g_wA[wbase + r];
                vb[r] = g_wB[wbase + r];
                sa += va[r]; sb += vb[r];
            }
            ia = sa; ib = sb;
#pragma unroll
            for (int off = 1; off < 32; off <<= 1) {
                float na = __shfl_up_sync(0xffffffffu, ia, off);
                float nb = __shfl_up_sync(0xffffffffu, ib, off);
                if (lane >= off) { ia += na; ib += nb; }
            }
            if (lane == 31) { sa_sh[w] = ia; sb_sh[w] = ib; }
        }
        __syncthreads();
        if (t < 128) {
            const int c = t;
            const int w = c >> 5;
            float offA = 0.f, offB = 0.f;
#pragma unroll
            for (int ww = 0; ww < 4; ww++)
                if (ww < w) { offA += sa_sh[ww]; offB += sb_sh[ww]; }
            float ra = offA + ia - sa;
            float rb = offB + ib - sb;
#pragma unroll
            for (int r = 0; r < CSZ; r++) {
                g_paf[b*NP + c*CSZ + r] = ra;
                g_pbf[b*NP + c*CSZ + r] = rb;
                ra += va[r]; rb += vb[r];
            }
            if (c == 127) {
                g_paf[b*NP + NN] = ra;
                g_pbf[b*NP + NN] = rb;
            }
        }
    }
}

// ---------------- Kernel 5: per-query output (base + relative prefix) ----------------
__global__ void __launch_bounds__(128) query_kernel(float* __restrict__ out)
{
    __shared__ float s2sh[NN];
    __shared__ int   ks[16];
    __shared__ float s1s[16];
    const int b = blockIdx.y, f = threadIdx.x;
    const int qbase = blockIdx.x * 16;
    for (int i = f; i < NN; i += 128) s2sh[i] = g_s2s[b*NN + i];
    __syncthreads();

    if (f < 16) {
        const int i = qbase + f;
        const float s1v = g_s1[b*NN + i];
        s1s[f] = s1v;
        const float t = -s1v;
        int k = 0;
#pragma unroll
        for (int st = 2048; st > 0; st >>= 1) {
            int nk = k + st;
            if (nk <= NN && s2sh[nk-1] <= t) k = nk;
        }
        ks[f] = k;
    }
    __syncthreads();

    const float m2v = g_m2[b];
    const float taf = g_ch[(size_t)(b*(NCH+1)+NCH)*NC + f].x;
    const float tas = g_paf[b*NP + NN];

#pragma unroll 4
    for (int qi = 0; qi < 16; qi++) {
        const int i = qbase + qi;
        const int k = ks[qi];
        const float s1v = s1s[qi];
        const int c = k >> 4;                    // k==NN -> c==NCH (totals base)
        const float2 bse = g_ch[(size_t)(b*(NCH+1)+c)*NC + f];
        const float2 rel = g_P[(size_t)(b*NP + k)*NC + f];
        const float PAk = bse.x + rel.x;
        const float PBk = bse.y + rel.y;
        const float sap = g_paf[b*NP + k];
        const float sbp = g_pbf[b*NP + k];
        const float SA = taf - PAk, SB = PBk;
        const float sa = tas - sap, sb = sbp;
        const float u = s1v + m2v;
        float hp;
        if (u > 0.f) {
            float inv = expf(-0.8f * u);
            hp = (SA + inv*SB) / (sa + inv*sb);
        } else {
            float fc = expf(0.8f * u);
            hp = (fc*SA + SB) / (fc*sa + sb);
        }
        const float hvi = g_h[(size_t)(b*NN + i)*NC + f];
        const float x = hp + 0.2f * hvi;
        out[(size_t)(b*NN + i)*NC + f] = (x > 0.f) ? x : expm1f(x);
    }
}

// ---------------- launch ----------------
extern "C" void kernel_launch(void* const* d_in, const int* in_sizes, int n_in,
                              void* d_out, int out_size)
{
    int iText = 0, iW = 2, iA = 3;
    for (int i = 0; i < n_in; i++) {
        if (in_sizes[i] == NB*NN*NC) iText = i;
        else if (in_sizes[i] == NC*NC) iW = i;
        else if (in_sizes[i] == 2*NC) iA = i;
    }
    const float* text = (const float*)d_in[iText];
    const float* W    = (const float*)d_in[iW];
    const float* avec = (const float*)d_in[iA];
    float* out = (float*)d_out;

    gemm_kernel<<<dim3(NN/64, NB), 256>>>(text, W, avec);
    rank_kernel<<<dim3(16, NB), 128>>>();
    relexpand_kernel<<<dim3(NCH, NB), 128>>>();
    scanspf_kernel<<<dim3(NB, 17), 256>>>();
    query_kernel<<<dim3(NN/16, NB), 128>>>(out);
}

// round 12
// speedup vs baseline: 1.4286x; 1.4286x over previous
#include <cuda_runtime.h>
#include <math.h>
#include <float.h>

// Problem constants
#define NB 8
#define NN 2048
#define NC 128
#define NCH 128     // chunks per batch
#define CSZ 16      // chunk size (NCH*CSZ == NN)
#define NP (NN+1)   // prefix length 2049

// ---------------- scratch (device globals; no allocation) ----------------
__device__ float g_h[NB*NN*NC];        // h = text @ W
__device__ float g_s1[NB*NN];
__device__ float g_s2[NB*NN];
__device__ float g_s2s[NB*NN];         // sorted s2 (ascending, via rank scatter)
__device__ int   g_perm[NB*NN];        // permutation of sort
__device__ float g_wA[NB*NN];          // e^{s2s - m2}
__device__ float g_wB[NB*NN];          // e^{0.2(s2s - m2)}
__device__ float g_m2[NB];
__device__ float2 g_ch[NB*(NCH+1)*NC]; // chunk aggregates -> exclusive bases; [NCH]=totals
__device__ float g_paf[NB*NP];         // full scalar exclusive prefix of wA; [2048]=total
__device__ float g_pbf[NB*NP];
__device__ float2 g_P[NB*NP*NC];       // intra-chunk RELATIVE vector prefixes (x=A, y=B)

// ---------------- f32x2 packed-FMA helpers (sm_103a FFMA2) ----------------
__device__ __forceinline__ unsigned long long pack2(float x, float y) {
    unsigned long long r;
    asm("mov.b64 %0, {%1, %2};" : "=l"(r) : "f"(x), "f"(y));
    return r;
}
__device__ __forceinline__ void unpack2(unsigned long long v, float& x, float& y) {
    asm("mov.b64 {%0, %1}, %2;" : "=f"(x), "=f"(y) : "l"(v));
}
__device__ __forceinline__ void ffma2(unsigned long long& d, unsigned long long a, unsigned long long b) {
    asm("fma.rn.f32x2 %0, %1, %2, %0;" : "+l"(d) : "l"(a), "l"(b));
}

// ---------------- Kernel 1: GEMM h = text@W (f32x2), fused s1/s2 ----------------
__global__ void __launch_bounds__(256) gemm_kernel(const float* __restrict__ A,
                                                   const float* __restrict__ W,
                                                   const float* __restrict__ avec)
{
    __shared__ float As[16][64];
    __shared__ float Bs[16][128];
    const int b  = blockIdx.y;
    const int m0 = blockIdx.x * 64;
    const int tid = threadIdx.x;
    const int tx = tid & 31;
    const int ty = tid >> 5;
    const float* Ab = A + (size_t)(b*NN + m0) * NC;

    unsigned long long acc2[4][4];
#pragma unroll
    for (int p = 0; p < 4; p++)
#pragma unroll
        for (int j = 0; j < 4; j++) acc2[p][j] = 0ull;

    const int ar = tid >> 2;
    const int ac = (tid & 3) * 4;

    for (int k0 = 0; k0 < 128; k0 += 16) {
        float4 av = *(const float4*)(Ab + (size_t)ar*NC + k0 + ac);
        As[ac+0][ar] = av.x; As[ac+1][ar] = av.y;
        As[ac+2][ar] = av.z; As[ac+3][ar] = av.w;
#pragma unroll
        for (int it = 0; it < 2; it++) {
            int idx = tid + 256*it;
            int brr = idx >> 5, bcc = (idx & 31) * 4;
            *(float4*)&Bs[brr][bcc] = *(const float4*)(W + (size_t)(k0+brr)*NC + bcc);
        }
        __syncthreads();
#pragma unroll
        for (int kk = 0; kk < 16; kk++) {
            float4 a03 = *(const float4*)&As[kk][ty*8];
            float4 a47 = *(const float4*)&As[kk][ty*8 + 4];
            float4 bv  = *(const float4*)&Bs[kk][tx*4];
            unsigned long long ap[4];
            ap[0] = pack2(a03.x, a03.y); ap[1] = pack2(a03.z, a03.w);
            ap[2] = pack2(a47.x, a47.y); ap[3] = pack2(a47.z, a47.w);
            unsigned long long bd[4];
            bd[0] = pack2(bv.x, bv.x); bd[1] = pack2(bv.y, bv.y);
            bd[2] = pack2(bv.z, bv.z); bd[3] = pack2(bv.w, bv.w);
#pragma unroll
            for (int p = 0; p < 4; p++)
#pragma unroll
                for (int j = 0; j < 4; j++) ffma2(acc2[p][j], ap[p], bd[j]);
        }
        __syncthreads();
    }

    float acc[8][4];
#pragma unroll
    for (int p = 0; p < 4; p++)
#pragma unroll
        for (int j = 0; j < 4; j++) unpack2(acc2[p][j], acc[2*p][j], acc[2*p+1][j]);

    float a1[4], a2[4];
#pragma unroll
    for (int j = 0; j < 4; j++) { a1[j] = avec[tx*4+j]; a2[j] = avec[128 + tx*4+j]; }

#pragma unroll
    for (int i = 0; i < 8; i++) {
        int row = m0 + ty*8 + i;
        float4 v = make_float4(acc[i][0], acc[i][1], acc[i][2], acc[i][3]);
        *(float4*)(g_h + (size_t)(b*NN + row)*NC + tx*4) = v;
        float d1 = acc[i][0]*a1[0] + acc[i][1]*a1[1] + acc[i][2]*a1[2] + acc[i][3]*a1[3];
        float d2 = acc[i][0]*a2[0] + acc[i][1]*a2[1] + acc[i][2]*a2[2] + acc[i][3]*a2[3];
#pragma unroll
        for (int off = 16; off > 0; off >>= 1) {
            d1 += __shfl_down_sync(0xffffffffu, d1, off);
            d2 += __shfl_down_sync(0xffffffffu, d2, off);
        }
        if (tx == 0) { g_s1[b*NN + row] = d1; g_s2[b*NN + row] = d2; }
    }
}

// ---------------- Kernel 2: rank-scatter "sort" (whole-chip parallel) ----------------
__global__ void __launch_bounds__(128) rank_kernel()
{
    __shared__ float keys[NN];
    __shared__ float red[4];
    const int b = blockIdx.y, tid = threadIdx.x;
    const int j = blockIdx.x * 128 + tid;

    for (int i = tid; i < NN; i += 128) keys[i] = g_s2[b*NN + i];
    __syncthreads();

    float mx = -FLT_MAX;
    for (int i = tid; i < NN; i += 128) mx = fmaxf(mx, keys[i]);
#pragma unroll
    for (int off = 16; off > 0; off >>= 1)
        mx = fmaxf(mx, __shfl_xor_sync(0xffffffffu, mx, off));
    if ((tid & 31) == 0) red[tid >> 5] = mx;
    __syncthreads();
    const float m2v = fmaxf(fmaxf(red[0], red[1]), fmaxf(red[2], red[3]));
    if (blockIdx.x == 0 && tid == 0) g_m2[b] = m2v;

    const float k = keys[j];
    const float4* k4 = (const float4*)keys;
    int rank = 0;
#pragma unroll 4
    for (int q = 0; q < NN/4; q++) {
        float4 v = k4[q];
        int jj = q*4;
        rank += (v.x < k) || (v.x == k && jj+0 < j);
        rank += (v.y < k) || (v.y == k && jj+1 < j);
        rank += (v.z < k) || (v.z == k && jj+2 < j);
        rank += (v.w < k) || (v.w == k && jj+3 < j);
    }

    const float s = k - m2v;
    const int o = b*NN + rank;
    g_s2s[o]  = k;
    g_perm[o] = j;
    g_wA[o]   = expf(s);
    g_wB[o]   = expf(0.2f * s);
}

// ---------------- Kernel 3: relative expand (single pass over h) ----------------
__global__ void __launch_bounds__(128) relexpand_kernel()
{
    __shared__ float wa[CSZ], wb[CSZ];
    __shared__ int js[CSZ];
    const int b = blockIdx.y, c = blockIdx.x, f = threadIdx.x;
    const int base = b*NN + c*CSZ;
    if (f < CSZ) {
        wa[f] = g_wA[base + f];
        wb[f] = g_wB[base + f];
        js[f] = g_perm[base + f];
    }
    __syncthreads();

    float hv[CSZ];
#pragma unroll
    for (int r = 0; r < CSZ; r++) hv[r] = g_h[(size_t)(b*NN + js[r])*NC + f];

    float runA = 0.f, runB = 0.f;
    size_t p = (size_t)(b*NP + c*CSZ)*NC + f;
#pragma unroll
    for (int r = 0; r < CSZ; r++) {
        g_P[p] = make_float2(runA, runB);
        runA = fmaf(wa[r], hv[r], runA);
        runB = fmaf(wb[r], hv[r], runB);
        p += NC;
    }
    g_ch[(size_t)(b*(NCH+1)+c)*NC + f] = make_float2(runA, runB);
    if (c == NCH-1) g_P[p] = make_float2(0.f, 0.f);
}

// ---------------- Kernel 4: warp-per-feature exclusive scan over 128 chunks ----------------
// grid (NB, 16) x 256 = 128 blocks; warp w handles feature f = by*8 + w
__global__ void __launch_bounds__(256) scan_kernel()
{
    const int b = blockIdx.x;
    const int w = threadIdx.x >> 5, lane = threadIdx.x & 31;
    const int f = blockIdx.y * 8 + w;
    const size_t base = (size_t)(b*(NCH+1))*NC + f;

    float2 v[4];
#pragma unroll
    for (int u = 0; u < 4; u++) v[u] = g_ch[base + (size_t)(lane*4+u)*NC];

    float ownA = (v[0].x + v[1].x) + (v[2].x + v[3].x);
    float ownB = (v[0].y + v[1].y) + (v[2].y + v[3].y);
    float sA = ownA, sB = ownB;
#pragma unroll
    for (int off = 1; off < 32; off <<= 1) {
        float nA = __shfl_up_sync(0xffffffffu, sA, off);
        float nB = __shfl_up_sync(0xffffffffu, sB, off);
        if (lane >= off) { sA += nA; sB += nB; }
    }
    float eA = sA - ownA, eB = sB - ownB;
#pragma unroll
    for (int u = 0; u < 4; u++) {
        float2 cur = v[u];
        g_ch[base + (size_t)(lane*4+u)*NC] = make_float2(eA, eB);
        eA += cur.x; eB += cur.y;
    }
    if (lane == 31) g_ch[base + (size_t)NCH*NC] = make_float2(sA, sB);
}

// ---------------- Kernel 5: scalar weight prefixes (per batch) ----------------
__global__ void __launch_bounds__(128) spf_kernel()
{
    __shared__ float sa_sh[4], sb_sh[4];
    const int b = blockIdx.x, c = threadIdx.x;
    const int lane = c & 31, w = c >> 5;
    const int base = b*NN + c*CSZ;

    float va[CSZ], vb[CSZ];
    float sa = 0.f, sb = 0.f;
#pragma unroll
    for (int r = 0; r < CSZ; r++) {
        va[r] = g_wA[base + r];
        vb[r] = g_wB[base + r];
        sa += va[r]; sb += vb[r];
    }
    float ia = sa, ib = sb;
#pragma unroll
    for (int off = 1; off < 32; off <<= 1) {
        float na = __shfl_up_sync(0xffffffffu, ia, off);
        float nb = __shfl_up_sync(0xffffffffu, ib, off);
        if (lane >= off) { ia += na; ib += nb; }
    }
    if (lane == 31) { sa_sh[w] = ia; sb_sh[w] = ib; }
    __syncthreads();
    float offA = 0.f, offB = 0.f;
#pragma unroll
    for (int ww = 0; ww < 4; ww++)
        if (ww < w) { offA += sa_sh[ww]; offB += sb_sh[ww]; }
    float ra = offA + ia - sa;
    float rb = offB + ib - sb;
#pragma unroll
    for (int r = 0; r < CSZ; r++) {
        g_paf[b*NP + c*CSZ + r] = ra;
        g_pbf[b*NP + c*CSZ + r] = rb;
        ra += va[r]; rb += vb[r];
    }
    if (c == 127) {
        g_paf[b*NP + NN] = ra;
        g_pbf[b*NP + NN] = rb;
    }
}

// ---------------- Kernel 6: per-query output (base + relative prefix) ----------------
__global__ void __launch_bounds__(128) query_kernel(float* __restrict__ out)
{
    __shared__ float s2sh[NN];
    __shared__ int   ks[16];
    __shared__ float s1s[16];
    const int b = blockIdx.y, f = threadIdx.x;
    const int qbase = blockIdx.x * 16;
    for (int i = f; i < NN; i += 128) s2sh[i] = g_s2s[b*NN + i];
    __syncthreads();

    if (f < 16) {
        const int i = qbase + f;
        const float s1v = g_s1[b*NN + i];
        s1s[f] = s1v;
        const float t = -s1v;
        int k = 0;
#pragma unroll
        for (int st = 2048; st > 0; st >>= 1) {
            int nk = k + st;
            if (nk <= NN && s2sh[nk-1] <= t) k = nk;
        }
        ks[f] = k;
    }
    __syncthreads();

    const float m2v = g_m2[b];
    const float taf = g_ch[(size_t)(b*(NCH+1)+NCH)*NC + f].x;
    const float tas = g_paf[b*NP + NN];

#pragma unroll 4
    for (int qi = 0; qi < 16; qi++) {
        const int i = qbase + qi;
        const int k = ks[qi];
        const float s1v = s1s[qi];
        const int c = k >> 4;                    // k==NN -> c==NCH (totals base)
        const float2 bse = g_ch[(size_t)(b*(NCH+1)+c)*NC + f];
        const float2 rel = g_P[(size_t)(b*NP + k)*NC + f];
        const float PAk = bse.x + rel.x;
        const float PBk = bse.y + rel.y;
        const float sap = g_paf[b*NP + k];
        const float sbp = g_pbf[b*NP + k];
        const float SA = taf - PAk, SB = PBk;
        const float sa = tas - sap, sb = sbp;
        const float u = s1v + m2v;
        float hp;
        if (u > 0.f) {
            float inv = expf(-0.8f * u);
            hp = (SA + inv*SB) / (sa + inv*sb);
        } else {
            float fc = expf(0.8f * u);
            hp = (fc*SA + SB) / (fc*sa + sb);
        }
        const float hvi = g_h[(size_t)(b*NN + i)*NC + f];
        const float x = hp + 0.2f * hvi;
        out[(size_t)(b*NN + i)*NC + f] = (x > 0.f) ? x : expm1f(x);
    }
}

// ---------------- launch ----------------
extern "C" void kernel_launch(void* const* d_in, const int* in_sizes, int n_in,
                              void* d_out, int out_size)
{
    int iText = 0, iW = 2, iA = 3;
    for (int i = 0; i < n_in; i++) {
        if (in_sizes[i] == NB*NN*NC) iText = i;
        else if (in_sizes[i] == NC*NC) iW = i;
        else if (in_sizes[i] == 2*NC) iA = i;
    }
    const float* text = (const float*)d_in[iText];
    const float* W    = (const float*)d_in[iW];
    const float* avec = (const float*)d_in[iA];
    float* out = (float*)d_out;

    gemm_kernel<<<dim3(NN/64, NB), 256>>>(text, W, avec);
    rank_kernel<<<dim3(16, NB), 128>>>();
    relexpand_kernel<<<dim3(NCH, NB), 128>>>();
    scan_kernel<<<dim3(NB, 16), 256>>>();
    spf_kernel<<<NB, 128>>>();
    query_kernel<<<dim3(NN/16, NB), 128>>>(out);
}

// round 14
// speedup vs baseline: 1.5289x; 1.0702x over previous
#include <cuda_runtime.h>
#include <math.h>
#include <float.h>

// Problem constants
#define NB 8
#define NN 2048
#define NC 128
#define NCH 128     // chunks per batch
#define CSZ 16      // chunk size (NCH*CSZ == NN)
#define NP (NN+1)   // prefix length 2049

// ---------------- scratch (device globals; no allocation) ----------------
__device__ float g_h[NB*NN*NC];        // h = text @ W
__device__ float g_s1[NB*NN];
__device__ float g_s2[NB*NN];
__device__ float g_s2s[NB*NN];         // sorted s2 (ascending, via rank scatter)
__device__ int   g_perm[NB*NN];        // permutation of sort
__device__ float g_wA[NB*NN];          // e^{s2s - m2}
__device__ float g_wB[NB*NN];          // e^{0.2(s2s - m2)}
__device__ float g_m2[NB];
__device__ float2 g_chT[NB*NC*NCH];    // TRANSPOSED chunk aggregates [b][f][c]
__device__ float2 g_ch[NB*(NCH+1)*NC]; // exclusive bases (written by scan); [NCH]=totals
__device__ float2 g_sagg[NB*NCH];      // scalar chunk aggregates (wA,wB sums)
__device__ float2 g_sch[NB*(NCH+1)];   // scalar exclusive bases; [NCH]=totals
__device__ float2 g_srel[NB*NP];       // intra-chunk relative scalar prefixes
__device__ float2 g_P[NB*NP*NC];       // intra-chunk RELATIVE vector prefixes (x=A, y=B)

// ---------------- f32x2 packed-FMA helpers (sm_103a FFMA2) ----------------
__device__ __forceinline__ unsigned long long pack2(float x, float y) {
    unsigned long long r;
    asm("mov.b64 %0, {%1, %2};" : "=l"(r) : "f"(x), "f"(y));
    return r;
}
__device__ __forceinline__ void unpack2(unsigned long long v, float& x, float& y) {
    asm("mov.b64 {%0, %1}, %2;" : "=f"(x), "=f"(y) : "l"(v));
}
__device__ __forceinline__ void ffma2(unsigned long long& d, unsigned long long a, unsigned long long b) {
    asm("fma.rn.f32x2 %0, %1, %2, %0;" : "+l"(d) : "l"(a), "l"(b));
}

// ---------------- Kernel 1: GEMM h = text@W (f32x2), fused s1/s2 ----------------
__global__ void __launch_bounds__(256) gemm_kernel(const float* __restrict__ A,
                                                   const float* __restrict__ W,
                                                   const float* __restrict__ avec)
{
    __shared__ float As[16][64];
    __shared__ float Bs[16][128];
    const int b  = blockIdx.y;
    const int m0 = blockIdx.x * 64;
    const int tid = threadIdx.x;
    const int tx = tid & 31;
    const int ty = tid >> 5;
    const float* Ab = A + (size_t)(b*NN + m0) * NC;

    unsigned long long acc2[4][4];
#pragma unroll
    for (int p = 0; p < 4; p++)
#pragma unroll
        for (int j = 0; j < 4; j++) acc2[p][j] = 0ull;

    const int ar = tid >> 2;
    const int ac = (tid & 3) * 4;

    for (int k0 = 0; k0 < 128; k0 += 16) {
        float4 av = *(const float4*)(Ab + (size_t)ar*NC + k0 + ac);
        As[ac+0][ar] = av.x; As[ac+1][ar] = av.y;
        As[ac+2][ar] = av.z; As[ac+3][ar] = av.w;
#pragma unroll
        for (int it = 0; it < 2; it++) {
            int idx = tid + 256*it;
            int brr = idx >> 5, bcc = (idx & 31) * 4;
            *(float4*)&Bs[brr][bcc] = *(const float4*)(W + (size_t)(k0+brr)*NC + bcc);
        }
        __syncthreads();
#pragma unroll
        for (int kk = 0; kk < 16; kk++) {
            float4 a03 = *(const float4*)&As[kk][ty*8];
            float4 a47 = *(const float4*)&As[kk][ty*8 + 4];
            float4 bv  = *(const float4*)&Bs[kk][tx*4];
            unsigned long long ap[4];
            ap[0] = pack2(a03.x, a03.y); ap[1] = pack2(a03.z, a03.w);
            ap[2] = pack2(a47.x, a47.y); ap[3] = pack2(a47.z, a47.w);
            unsigned long long bd[4];
            bd[0] = pack2(bv.x, bv.x); bd[1] = pack2(bv.y, bv.y);
            bd[2] = pack2(bv.z, bv.z); bd[3] = pack2(bv.w, bv.w);
#pragma unroll
            for (int p = 0; p < 4; p++)
#pragma unroll
                for (int j = 0; j < 4; j++) ffma2(acc2[p][j], ap[p], bd[j]);
        }
        __syncthreads();
    }

    float acc[8][4];
#pragma unroll
    for (int p = 0; p < 4; p++)
#pragma unroll
        for (int j = 0; j < 4; j++) unpack2(acc2[p][j], acc[2*p][j], acc[2*p+1][j]);

    float a1[4], a2[4];
#pragma unroll
    for (int j = 0; j < 4; j++) { a1[j] = avec[tx*4+j]; a2[j] = avec[128 + tx*4+j]; }

#pragma unroll
    for (int i = 0; i < 8; i++) {
        int row = m0 + ty*8 + i;
        float4 v = make_float4(acc[i][0], acc[i][1], acc[i][2], acc[i][3]);
        *(float4*)(g_h + (size_t)(b*NN + row)*NC + tx*4) = v;
        float d1 = acc[i][0]*a1[0] + acc[i][1]*a1[1] + acc[i][2]*a1[2] + acc[i][3]*a1[3];
        float d2 = acc[i][0]*a2[0] + acc[i][1]*a2[1] + acc[i][2]*a2[2] + acc[i][3]*a2[3];
#pragma unroll
        for (int off = 16; off > 0; off >>= 1) {
            d1 += __shfl_down_sync(0xffffffffu, d1, off);
            d2 += __shfl_down_sync(0xffffffffu, d2, off);
        }
        if (tx == 0) { g_s1[b*NN + row] = d1; g_s2[b*NN + row] = d2; }
    }
}

// ---------------- Kernel 2: rank-scatter "sort" (whole-chip parallel) ----------------
__global__ void __launch_bounds__(128) rank_kernel()
{
    __shared__ float keys[NN];
    __shared__ float red[4];
    const int b = blockIdx.y, tid = threadIdx.x;
    const int j = blockIdx.x * 128 + tid;

    for (int i = tid; i < NN; i += 128) keys[i] = g_s2[b*NN + i];
    __syncthreads();

    float mx = -FLT_MAX;
    for (int i = tid; i < NN; i += 128) mx = fmaxf(mx, keys[i]);
#pragma unroll
    for (int off = 16; off > 0; off >>= 1)
        mx = fmaxf(mx, __shfl_xor_sync(0xffffffffu, mx, off));
    if ((tid & 31) == 0) red[tid >> 5] = mx;
    __syncthreads();
    const float m2v = fmaxf(fmaxf(red[0], red[1]), fmaxf(red[2], red[3]));
    if (blockIdx.x == 0 && tid == 0) g_m2[b] = m2v;

    const float k = keys[j];
    const float4* k4 = (const float4*)keys;
    int rank = 0;
#pragma unroll 4
    for (int q = 0; q < NN/4; q++) {
        float4 v = k4[q];
        int jj = q*4;
        rank += (v.x < k) || (v.x == k && jj+0 < j);
        rank += (v.y < k) || (v.y == k && jj+1 < j);
        rank += (v.z < k) || (v.z == k && jj+2 < j);
        rank += (v.w < k) || (v.w == k && jj+3 < j);
    }

    const float s = k - m2v;
    const int o = b*NN + rank;
    g_s2s[o]  = k;
    g_perm[o] = j;
    g_wA[o]   = expf(s);
    g_wB[o]   = expf(0.2f * s);
}

// ---------------- Kernel 3: relative expand + transposed aggregates + scalar rels ----------------
__global__ void __launch_bounds__(128) relexpand_kernel()
{
    __shared__ float wa[CSZ], wb[CSZ];
    __shared__ int js[CSZ];
    const int b = blockIdx.y, c = blockIdx.x, f = threadIdx.x;
    const int base = b*NN + c*CSZ;
    if (f < CSZ) {
        wa[f] = g_wA[base + f];
        wb[f] = g_wB[base + f];
        js[f] = g_perm[base + f];
    }
    __syncthreads();

    float hv[CSZ];
#pragma unroll
    for (int r = 0; r < CSZ; r++) hv[r] = g_h[(size_t)(b*NN + js[r])*NC + f];

    float runA = 0.f, runB = 0.f;
    size_t p = (size_t)(b*NP + c*CSZ)*NC + f;
#pragma unroll
    for (int r = 0; r < CSZ; r++) {
        g_P[p] = make_float2(runA, runB);
        runA = fmaf(wa[r], hv[r], runA);
        runB = fmaf(wb[r], hv[r], runB);
        p += NC;
    }
    // transposed aggregate for the scan's coalesced read
    g_chT[(size_t)(b*NC + f)*NCH + c] = make_float2(runA, runB);
    if (c == NCH-1) g_P[p] = make_float2(0.f, 0.f);

    // scalar relative prefixes + aggregate (thread 0 only; 16 cheap serial steps)
    if (f == 0) {
        float ra = 0.f, rb = 0.f;
#pragma unroll
        for (int r = 0; r < CSZ; r++) {
            g_srel[b*NP + c*CSZ + r] = make_float2(ra, rb);
            ra += wa[r]; rb += wb[r];
        }
        g_sagg[b*NCH + c] = make_float2(ra, rb);
        if (c == NCH-1) g_srel[b*NP + NN] = make_float2(0.f, 0.f);
    }
}

// ---------------- Kernel 4: coalesced scan (vector + scalar) ----------------
// grid (NB, 16) x 256; warp w scans feature f = y*8+w from transposed layout
// (contiguous 1KB per feature), writes exclusive bases in normal layout.
// Block y==0 warp 0 additionally scans the scalar aggregates.
__global__ void __launch_bounds__(256) scan_kernel()
{
    const int b = blockIdx.x;
    const int w = threadIdx.x >> 5, lane = threadIdx.x & 31;
    const int f = blockIdx.y * 8 + w;
    const size_t tb = (size_t)(b*NC + f)*NCH;

    float2 v[4];
#pragma unroll
    for (int u = 0; u < 4; u++) v[u] = g_chT[tb + lane*4 + u];

    float ownA = (v[0].x + v[1].x) + (v[2].x + v[3].x);
    float ownB = (v[0].y + v[1].y) + (v[2].y + v[3].y);
    float sA = ownA, sB = ownB;
#pragma unroll
    for (int off = 1; off < 32; off <<= 1) {
        float nA = __shfl_up_sync(0xffffffffu, sA, off);
        float nB = __shfl_up_sync(0xffffffffu, sB, off);
        if (lane >= off) { sA += nA; sB += nB; }
    }
    float eA = sA - ownA, eB = sB - ownB;
#pragma unroll
    for (int u = 0; u < 4; u++) {
        g_ch[(size_t)(b*(NCH+1) + lane*4 + u)*NC + f] = make_float2(eA, eB);
        eA += v[u].x; eB += v[u].y;
    }
    if (lane == 31) g_ch[(size_t)(b*(NCH+1)+NCH)*NC + f] = make_float2(sA, sB);

    // scalar aggregates scan (one warp total)
    if (blockIdx.y == 0 && w == 0) {
        float2 s[4];
#pragma unroll
        for (int u = 0; u < 4; u++) s[u] = g_sagg[b*NCH + lane*4 + u];
        float oA = (s[0].x + s[1].x) + (s[2].x + s[3].x);
        float oB = (s[0].y + s[1].y) + (s[2].y + s[3].y);
        float tA = oA, tB = oB;
#pragma unroll
        for (int off = 1; off < 32; off <<= 1) {
            float nA = __shfl_up_sync(0xffffffffu, tA, off);
            float nB = __shfl_up_sync(0xffffffffu, tB, off);
            if (lane >= off) { tA += nA; tB += nB; }
        }
        float xA = tA - oA, xB = tB - oB;
#pragma unroll
        for (int u = 0; u < 4; u++) {
            g_sch[b*(NCH+1) + lane*4 + u] = make_float2(xA, xB);
            xA += s[u].x; xB += s[u].y;
        }
        if (lane == 31) g_sch[b*(NCH+1)+NCH] = make_float2(tA, tB);
    }
}

// ---------------- Kernel 5: per-query output (base + relative prefix) ----------------
__global__ void __launch_bounds__(128) query_kernel(float* __restrict__ out)
{
    __shared__ float s2sh[NN];
    __shared__ int   ks[16];
    __shared__ float s1s[16];
    const int b = blockIdx.y, f = threadIdx.x;
    const int qbase = blockIdx.x * 16;
    for (int i = f; i < NN; i += 128) s2sh[i] = g_s2s[b*NN + i];
    __syncthreads();

    if (f < 16) {
        const int i = qbase + f;
        const float s1v = g_s1[b*NN + i];
        s1s[f] = s1v;
        const float t = -s1v;
        int k = 0;
#pragma unroll
        for (int st = 2048; st > 0; st >>= 1) {
            int nk = k + st;
            if (nk <= NN && s2sh[nk-1] <= t) k = nk;
        }
        ks[f] = k;
    }
    __syncthreads();

    const float m2v = g_m2[b];
    const float taf = g_ch[(size_t)(b*(NCH+1)+NCH)*NC + f].x;
    const float tas = g_sch[b*(NCH+1)+NCH].x;

#pragma unroll 4
    for (int qi = 0; qi < 16; qi++) {
        const int i = qbase + qi;
        const int k = ks[qi];
        const float s1v = s1s[qi];
        const int c = k >> 4;                    // k==NN -> c==NCH (totals base)
        const float2 bse = g_ch[(size_t)(b*(NCH+1)+c)*NC + f];
        const float2 rel = g_P[(size_t)(b*NP + k)*NC + f];
        const float2 sb2 = g_sch[b*(NCH+1)+c];
        const float2 sr2 = g_srel[b*NP + k];
        const float PAk = bse.x + rel.x;
        const float PBk = bse.y + rel.y;
        const float sap = sb2.x + sr2.x;
        const float sbp = sb2.y + sr2.y;
        const float SA = taf - PAk, SB = PBk;
        const float sa = tas - sap, sb = sbp;
        const float u = s1v + m2v;
        float hp;
        if (u > 0.f) {
            float inv = expf(-0.8f * u);
            hp = (SA + inv*SB) / (sa + inv*sb);
        } else {
            float fc = expf(0.8f * u);
            hp = (fc*SA + SB) / (fc*sa + sb);
        }
        const float hvi = g_h[(size_t)(b*NN + i)*NC + f];
        const float x = hp + 0.2f * hvi;
        out[(size_t)(b*NN + i)*NC + f] = (x > 0.f) ? x : expm1f(x);
    }
}

// ---------------- launch ----------------
extern "C" void kernel_launch(void* const* d_in, const int* in_sizes, int n_in,
                              void* d_out, int out_size)
{
    int iText = 0, iW = 2, iA = 3;
    for (int i = 0; i < n_in; i++) {
        if (in_sizes[i] == NB*NN*NC) iText = i;
        else if (in_sizes[i] == NC*NC) iW = i;
        else if (in_sizes[i] == 2*NC) iA = i;
    }
    const float* text = (const float*)d_in[iText];
    const float* W    = (const float*)d_in[iW];
    const float* avec = (const float*)d_in[iA];
    float* out = (float*)d_out;

    gemm_kernel<<<dim3(NN/64, NB), 256>>>(text, W, avec);
    rank_kernel<<<dim3(16, NB), 128>>>();
    relexpand_kernel<<<dim3(NCH, NB), 128>>>();
    scan_kernel<<<dim3(NB, 16), 256>>>();
    query_kernel<<<dim3(NN/16, NB), 128>>>(out);
}